// round 14
// baseline (speedup 1.0000x reference)
#include <cuda_runtime.h>
#include <math.h>
#include <stdint.h>

#define B 64
#define S 512
#define H 768
#define K 64

// Scratch
__device__ float g_pooled[3 * B * H];

__device__ __forceinline__ void cp16(void* dst_smem, const void* src) {
    uint32_t d = (uint32_t)__cvta_generic_to_shared(dst_smem);
    asm volatile("cp.async.cg.shared.global [%0], [%1], 16;" :: "r"(d), "l"(src) : "memory");
}
__device__ __forceinline__ void cp_commit() {
    asm volatile("cp.async.commit_group;" ::: "memory");
}
template<int N> __device__ __forceinline__ void cp_wait() {
    asm volatile("cp.async.wait_group %0;" :: "n"(N) : "memory");
}

// ---------------------------------------------------------------------------
// K1: fused scores + softmax + pool. grid (B, 3, 3 htiles of 256), block 256.
// (proven R13 body)
// ---------------------------------------------------------------------------
__global__ void __launch_bounds__(256)
attn_pool_kernel(const float* __restrict__ seq,
                 const int* __restrict__ idx0, const int* __restrict__ len0,
                 const int* __restrict__ idx1, const int* __restrict__ len1,
                 const int* __restrict__ idx2, const int* __restrict__ len2,
                 const float* __restrict__ bc0,
                 const float* __restrict__ bc1,
                 const float* __restrict__ bc2,
                 float* __restrict__ out) {
    int b  = blockIdx.x;
    int t  = blockIdx.y;
    int zt = blockIdx.z;           // h-tile: h0 = zt*256
    const int* idxp = (t == 0) ? idx0 : (t == 1) ? idx1 : idx2;
    const int* lenp = (t == 0) ? len0 : (t == 1) ? len1 : len2;

    __shared__ float4 g0s[192];    // row 0 (768 floats)
    __shared__ float  scr[K];
    __shared__ float  prob[K];
    __shared__ int    sidx[K];

    int tid  = threadIdx.x;
    int wid  = tid >> 5;
    int lane = tid & 31;

    // bias init (layout: rel 64x9 | nov 64x3 | dir 64x3)
    if (b == 0 && t == 0 && zt == 0) {
        for (int i = tid; i < 960; i += 256) {
            float v;
            if (i < 576)      v = bc0[i % 9];
            else if (i < 768) v = bc1[(i - 576) % 3];
            else              v = bc2[(i - 768) % 3];
            out[i] = v;
        }
    }

    int len = lenp[b];
    if (tid < K) sidx[tid] = idxp[b * K + tid];
    __syncthreads();

    const float* seqb = seq + (size_t)b * S * H;
    int h = zt * 256 + tid;

    if (len == 0) {   // fallback: seq[b, 0, :]
        g_pooled[((size_t)t * B + b) * H + h] = seqb[h];
        return;
    }

    int si0 = sidx[0];
    if (tid < 192) g0s[tid] = ((const float4*)(seqb + (size_t)si0 * H))[tid];
    __syncthreads();

    // ---- Phase 1: scores. Warp wid covers j in {8w..8w+7} as pairs (j, j+4).
    for (int p = 0; p < 4; p++) {
        int ja = 8 * wid + p;
        if (ja >= len) break;                 // warp-uniform
        int jb = ja + 4;
        bool dob = (jb < len);
        const float4* ga = (const float4*)(seqb + (size_t)sidx[ja] * H);
        const float4* gb = (const float4*)(seqb + (size_t)sidx[dob ? jb : ja] * H);

        float4 av[6], bv[6];
        if (dob) {
            #pragma unroll
            for (int i = 0; i < 6; i++) { av[i] = ga[lane + 32 * i]; bv[i] = gb[lane + 32 * i]; }
        } else {
            #pragma unroll
            for (int i = 0; i < 6; i++) { av[i] = ga[lane + 32 * i]; bv[i] = make_float4(0,0,0,0); }
        }

        float sa = 0.f, sb = 0.f;
        #pragma unroll
        for (int i = 0; i < 6; i++) {
            float4 g0v = g0s[lane + 32 * i];
            sa += g0v.x * av[i].x + g0v.y * av[i].y
                + g0v.z * av[i].z + g0v.w * av[i].w;
            sb += g0v.x * bv[i].x + g0v.y * bv[i].y
                + g0v.z * bv[i].z + g0v.w * bv[i].w;
        }
        #pragma unroll
        for (int o = 16; o; o >>= 1) {
            sa += __shfl_xor_sync(0xffffffffu, sa, o);
            sb += __shfl_xor_sync(0xffffffffu, sb, o);
        }
        if (lane == 0) {
            scr[ja] = sa;
            if (dob) scr[jb] = sb;
        }
    }
    __syncthreads();

    // ---- Phase 2: masked softmax (warp 0) ----
    if (tid < 32) {
        float sa = (lane      < len) ? scr[lane]      : -1e30f;
        float sb = (lane + 32 < len) ? scr[lane + 32] : -1e30f;
        float m = fmaxf(sa, sb);
        #pragma unroll
        for (int o = 16; o; o >>= 1) m = fmaxf(m, __shfl_xor_sync(0xffffffffu, m, o));
        float ea = (lane      < len) ? expf(sa - m) : 0.f;
        float eb = (lane + 32 < len) ? expf(sb - m) : 0.f;
        float sum = ea + eb;
        #pragma unroll
        for (int o = 16; o; o >>= 1) sum += __shfl_xor_sync(0xffffffffu, sum, o);
        float inv = 1.0f / sum;
        prob[lane]      = ea * inv;
        prob[lane + 32] = eb * inv;
    }
    __syncthreads();

    // ---- Phase 3: weighted sum for this h slice ----
    const float* base = seqb + h;
    float acc = 0.f;
    #pragma unroll 16
    for (int j = 0; j < len; j++) {
        acc += prob[j] * base[(size_t)sidx[j] * H];
    }
    g_pooled[((size_t)t * B + b) * H + h] = acc;
}

// ---------------------------------------------------------------------------
// K2: h = tanh(P @ Wd^T + bd) + fused classifier. dense v6:
//  - Pt padded [768][20]: STS staging 16-way -> 4-way; inner LDS.128 stays
//    conflict-free (16 consecutive words).
//  - inner loop per 4kk: 1x LDS.128 (W row) + 4x LDS.128 (P) + 16 FMA.
//  - KTILE=64 double-buffered cp.async; 12 tiles, 24 syncs.
// grid (12 rtiles of 64, 4 btiles of 16, 3), block 256 (8 warps).
// lane: row = 8*wid + (lane>>2); batches 4*(lane&3)..+3.
// ---------------------------------------------------------------------------
#define WPAD 68
#define PPAD 20
#define KTILE 64
#define DENSE_SMEM ((H * PPAD + 2 * 64 * WPAD + 16 * 66) * sizeof(float))  // 100480 B

__global__ void __launch_bounds__(256)
dense_kernel(const float* __restrict__ Wd0, const float* __restrict__ bd0,
             const float* __restrict__ Wd1, const float* __restrict__ bd1,
             const float* __restrict__ Wd2, const float* __restrict__ bd2,
             const float* __restrict__ Wc0,
             const float* __restrict__ Wc1,
             const float* __restrict__ Wc2,
             float* __restrict__ out) {
    extern __shared__ float dsm[];
    float* Pt = dsm;                        // [768][PPAD]
    float* Ws = dsm + H * PPAD;             // [2][64][WPAD]
    float* Hs = Ws + 2 * 64 * WPAD;         // [16][66]

    int t = blockIdx.z;
    const float* Wd = (t == 0) ? Wd0 : (t == 1) ? Wd1 : Wd2;
    const float* bd = (t == 0) ? bd0 : (t == 1) ? bd1 : bd2;
    const float* Wc = (t == 0) ? Wc0 : (t == 1) ? Wc1 : Wc2;
    int nlab   = (t == 0) ? 9 : 3;
    int outoff = (t == 0) ? 0 : (t == 1) ? B * 9 : B * 9 + B * 3;

    int r0 = blockIdx.x * 64;
    int b0 = blockIdx.y * 16;

    int tid  = threadIdx.x;
    int wid  = tid >> 5;
    int lane = tid & 31;
    int row  = 8 * wid + (lane >> 2);   // 0..63
    int bg   = lane & 3;                // batches 4bg..4bg+3

    const float* P = g_pooled + (size_t)t * B * H;

    // W tile staging map: 1024 float4/tile, 4/thread:
    //   f4id = tid + 256*i -> r = f4id>>4 (0..63), c4 = f4id&15 (0..15)
    int sr  = tid >> 4;
    int sc4 = tid & 15;

    // prologue: issue W tile 0
    {
        const float* src = Wd + (size_t)(r0 + sr) * H + 4 * sc4;
        #pragma unroll
        for (int i = 0; i < 4; i++)
            cp16(&Ws[(sr + 16 * i) * WPAD + 4 * sc4], src + (size_t)(16 * i) * H);
        cp_commit();
    }

    // stage P transposed into padded Pt (4-phase STS; overlaps tile-0 cp)
    #pragma unroll
    for (int i = 0; i < 48; i++) {
        int bb = i / 3;
        int k  = (i - 3 * bb) * 256 + tid;
        Pt[k * PPAD + bb] = P[(size_t)(b0 + bb) * H + k];
    }

    float acc0 = 0.f, acc1 = 0.f, acc2 = 0.f, acc3 = 0.f;
    const int NT = H / KTILE;   // 12 tiles

    for (int it = 0; it < NT; it++) {
        if (it + 1 < NT) {
            int k0n = (it + 1) * KTILE;
            float* dstb = Ws + ((it + 1) & 1) * 64 * WPAD;
            const float* src = Wd + (size_t)(r0 + sr) * H + k0n + 4 * sc4;
            #pragma unroll
            for (int i = 0; i < 4; i++)
                cp16(&dstb[(sr + 16 * i) * WPAD + 4 * sc4], src + (size_t)(16 * i) * H);
            cp_commit();
            cp_wait<1>();
        } else {
            cp_wait<0>();
        }
        __syncthreads();

        const float* Wrow = Ws + (it & 1) * 64 * WPAD + row * WPAD;
        const float* Pk   = Pt + (size_t)(it * KTILE) * PPAD + 4 * bg;
        #pragma unroll
        for (int g = 0; g < KTILE / 4; g++) {
            float4 wq = *(const float4*)&Wrow[4 * g];
            float4 p0 = *(const float4*)&Pk[(4 * g + 0) * PPAD];
            float4 p1 = *(const float4*)&Pk[(4 * g + 1) * PPAD];
            float4 p2 = *(const float4*)&Pk[(4 * g + 2) * PPAD];
            float4 p3 = *(const float4*)&Pk[(4 * g + 3) * PPAD];
            acc0 += wq.x * p0.x;  acc1 += wq.x * p0.y;
            acc2 += wq.x * p0.z;  acc3 += wq.x * p0.w;
            acc0 += wq.y * p1.x;  acc1 += wq.y * p1.y;
            acc2 += wq.y * p1.z;  acc3 += wq.y * p1.w;
            acc0 += wq.z * p2.x;  acc1 += wq.z * p2.y;
            acc2 += wq.z * p2.z;  acc3 += wq.z * p2.w;
            acc0 += wq.w * p3.x;  acc1 += wq.w * p3.y;
            acc2 += wq.w * p3.z;  acc3 += wq.w * p3.w;
        }
        __syncthreads();
    }

    // epilogue: tanh + bias -> Hs
    float bdr = __ldg(&bd[r0 + row]);
    Hs[(4 * bg + 0) * 66 + row] = tanhf(acc0 + bdr);
    Hs[(4 * bg + 1) * 66 + row] = tanhf(acc1 + bdr);
    Hs[(4 * bg + 2) * 66 + row] = tanhf(acc2 + bdr);
    Hs[(4 * bg + 3) * 66 + row] = tanhf(acc3 + bdr);
    __syncthreads();

    // fused classifier: warp wid handles batches 2wid, 2wid+1
    #pragma unroll
    for (int bb = 0; bb < 2; bb++) {
        int bl = 2 * wid + bb;
        float h0v = Hs[bl * 66 + lane];
        float h1v = Hs[bl * 66 + lane + 32];
        for (int l = 0; l < nlab; l++) {
            const float* wr = Wc + (size_t)l * H + r0;
            float s = h0v * __ldg(wr + lane) + h1v * __ldg(wr + lane + 32);
            #pragma unroll
            for (int o = 16; o; o >>= 1) s += __shfl_xor_sync(0xffffffffu, s, o);
            if (lane == 0)
                atomicAdd(&out[outoff + (b0 + bl) * nlab + l], s);
        }
    }
}

// ---------------------------------------------------------------------------
extern "C" void kernel_launch(void* const* d_in, const int* in_sizes, int n_in,
                              void* d_out, int out_size) {
    const float* seq      = (const float*)d_in[0];
    const int*   rel_idx  = (const int*)d_in[1];
    const int*   rel_len  = (const int*)d_in[2];
    const int*   nov_idx  = (const int*)d_in[3];
    const int*   nov_len  = (const int*)d_in[4];
    const int*   dir_idx  = (const int*)d_in[5];
    const int*   dir_len  = (const int*)d_in[6];
    const float* rel_dW   = (const float*)d_in[7];
    const float* rel_db   = (const float*)d_in[8];
    const float* rel_cW   = (const float*)d_in[9];
    const float* rel_cb   = (const float*)d_in[10];
    const float* nov_dW   = (const float*)d_in[11];
    const float* nov_db   = (const float*)d_in[12];
    const float* nov_cW   = (const float*)d_in[13];
    const float* nov_cb   = (const float*)d_in[14];
    const float* dir_dW   = (const float*)d_in[15];
    const float* dir_db   = (const float*)d_in[16];
    const float* dir_cW   = (const float*)d_in[17];
    const float* dir_cb   = (const float*)d_in[18];
    float* out = (float*)d_out;

    static int smem_set = 0;
    if (!smem_set) {
        cudaFuncSetAttribute(dense_kernel,
                             cudaFuncAttributeMaxDynamicSharedMemorySize,
                             DENSE_SMEM);
        smem_set = 1;
    }

    attn_pool_kernel<<<dim3(B, 3, 3), 256>>>(seq, rel_idx, rel_len,
                                             nov_idx, nov_len, dir_idx, dir_len,
                                             rel_cb, nov_cb, dir_cb, out);
    dense_kernel<<<dim3(12, 4, 3), 256, DENSE_SMEM>>>(rel_dW, rel_db, nov_dW, nov_db,
                                                      dir_dW, dir_db,
                                                      rel_cW, nov_cW, dir_cW, out);
}

// round 15
// speedup vs baseline: 1.0595x; 1.0595x over previous
#include <cuda_runtime.h>
#include <math.h>
#include <stdint.h>

#define B 64
#define S 512
#define H 768
#define K 64

// Scratch
__device__ float g_pooled[3 * B * H];

__device__ __forceinline__ void cp16(void* dst_smem, const void* src) {
    uint32_t d = (uint32_t)__cvta_generic_to_shared(dst_smem);
    asm volatile("cp.async.cg.shared.global [%0], [%1], 16;" :: "r"(d), "l"(src) : "memory");
}
__device__ __forceinline__ void cp_commit() {
    asm volatile("cp.async.commit_group;" ::: "memory");
}
template<int N> __device__ __forceinline__ void cp_wait() {
    asm volatile("cp.async.wait_group %0;" :: "n"(N) : "memory");
}

// ---------------------------------------------------------------------------
// K1: fused scores + softmax + pool. grid (B, 3, 3 htiles of 256), block 256.
// (proven R13 body)
// ---------------------------------------------------------------------------
__global__ void __launch_bounds__(256)
attn_pool_kernel(const float* __restrict__ seq,
                 const int* __restrict__ idx0, const int* __restrict__ len0,
                 const int* __restrict__ idx1, const int* __restrict__ len1,
                 const int* __restrict__ idx2, const int* __restrict__ len2,
                 const float* __restrict__ bc0,
                 const float* __restrict__ bc1,
                 const float* __restrict__ bc2,
                 float* __restrict__ out) {
    int b  = blockIdx.x;
    int t  = blockIdx.y;
    int zt = blockIdx.z;           // h-tile: h0 = zt*256
    const int* idxp = (t == 0) ? idx0 : (t == 1) ? idx1 : idx2;
    const int* lenp = (t == 0) ? len0 : (t == 1) ? len1 : len2;

    __shared__ float4 g0s[192];    // row 0 (768 floats)
    __shared__ float  scr[K];
    __shared__ float  prob[K];
    __shared__ int    sidx[K];

    int tid  = threadIdx.x;
    int wid  = tid >> 5;
    int lane = tid & 31;

    // bias init (layout: rel 64x9 | nov 64x3 | dir 64x3)
    if (b == 0 && t == 0 && zt == 0) {
        for (int i = tid; i < 960; i += 256) {
            float v;
            if (i < 576)      v = bc0[i % 9];
            else if (i < 768) v = bc1[(i - 576) % 3];
            else              v = bc2[(i - 768) % 3];
            out[i] = v;
        }
    }

    int len = lenp[b];
    if (tid < K) sidx[tid] = idxp[b * K + tid];
    __syncthreads();

    const float* seqb = seq + (size_t)b * S * H;
    int h = zt * 256 + tid;

    if (len == 0) {   // fallback: seq[b, 0, :]
        g_pooled[((size_t)t * B + b) * H + h] = seqb[h];
        return;
    }

    int si0 = sidx[0];
    if (tid < 192) g0s[tid] = ((const float4*)(seqb + (size_t)si0 * H))[tid];
    __syncthreads();

    // ---- Phase 1: scores. Warp wid covers j in {8w..8w+7} as pairs (j, j+4).
    for (int p = 0; p < 4; p++) {
        int ja = 8 * wid + p;
        if (ja >= len) break;                 // warp-uniform
        int jb = ja + 4;
        bool dob = (jb < len);
        const float4* ga = (const float4*)(seqb + (size_t)sidx[ja] * H);
        const float4* gb = (const float4*)(seqb + (size_t)sidx[dob ? jb : ja] * H);

        float4 av[6], bv[6];
        if (dob) {
            #pragma unroll
            for (int i = 0; i < 6; i++) { av[i] = ga[lane + 32 * i]; bv[i] = gb[lane + 32 * i]; }
        } else {
            #pragma unroll
            for (int i = 0; i < 6; i++) { av[i] = ga[lane + 32 * i]; bv[i] = make_float4(0,0,0,0); }
        }

        float sa = 0.f, sb = 0.f;
        #pragma unroll
        for (int i = 0; i < 6; i++) {
            float4 g0v = g0s[lane + 32 * i];
            sa += g0v.x * av[i].x + g0v.y * av[i].y
                + g0v.z * av[i].z + g0v.w * av[i].w;
            sb += g0v.x * bv[i].x + g0v.y * bv[i].y
                + g0v.z * bv[i].z + g0v.w * bv[i].w;
        }
        #pragma unroll
        for (int o = 16; o; o >>= 1) {
            sa += __shfl_xor_sync(0xffffffffu, sa, o);
            sb += __shfl_xor_sync(0xffffffffu, sb, o);
        }
        if (lane == 0) {
            scr[ja] = sa;
            if (dob) scr[jb] = sb;
        }
    }
    __syncthreads();

    // ---- Phase 2: masked softmax (warp 0) ----
    if (tid < 32) {
        float sa = (lane      < len) ? scr[lane]      : -1e30f;
        float sb = (lane + 32 < len) ? scr[lane + 32] : -1e30f;
        float m = fmaxf(sa, sb);
        #pragma unroll
        for (int o = 16; o; o >>= 1) m = fmaxf(m, __shfl_xor_sync(0xffffffffu, m, o));
        float ea = (lane      < len) ? expf(sa - m) : 0.f;
        float eb = (lane + 32 < len) ? expf(sb - m) : 0.f;
        float sum = ea + eb;
        #pragma unroll
        for (int o = 16; o; o >>= 1) sum += __shfl_xor_sync(0xffffffffu, sum, o);
        float inv = 1.0f / sum;
        prob[lane]      = ea * inv;
        prob[lane + 32] = eb * inv;
    }
    __syncthreads();

    // ---- Phase 3: weighted sum for this h slice ----
    const float* base = seqb + h;
    float acc = 0.f;
    #pragma unroll 16
    for (int j = 0; j < len; j++) {
        acc += prob[j] * base[(size_t)sidx[j] * H];
    }
    g_pooled[((size_t)t * B + b) * H + h] = acc;
}

// ---------------------------------------------------------------------------
// K2: h = tanh(P @ Wd^T + bd) + fused classifier. dense v7:
//  - thread tile 2 rows {tx, tx+32} x 2 batches {2wid, 2wid+1}
//  - k-vectorized: per 4kk -> 2x LDS.128 W + 2x LDS.128 P(broadcast) + 16 FMA
//    = 4 B smem / FMA (was 5) with 4x fewer load instrs
//  - Ws row stride 68 words: 32 distinct rows conflict-free for LDS.128
//  - P natural layout [16][772] (k-contiguous): trivial coalesced staging
//  - KTILE=64 double-buffered cp.async
// grid (12 rtiles of 64, 4 btiles of 16, 3), block 256 (8 warps).
// ---------------------------------------------------------------------------
#define WSTR 68
#define PSTR 772
#define KTILE 64
#define DENSE_SMEM ((16 * PSTR + 2 * 64 * WSTR + 16 * 66) * sizeof(float))  // 88448 B

__global__ void __launch_bounds__(256)
dense_kernel(const float* __restrict__ Wd0, const float* __restrict__ bd0,
             const float* __restrict__ Wd1, const float* __restrict__ bd1,
             const float* __restrict__ Wd2, const float* __restrict__ bd2,
             const float* __restrict__ Wc0,
             const float* __restrict__ Wc1,
             const float* __restrict__ Wc2,
             float* __restrict__ out) {
    extern __shared__ float dsm[];
    float* Pn = dsm;                        // [16][PSTR]
    float* Ws = dsm + 16 * PSTR;            // [2][64][WSTR]
    float* Hs = Ws + 2 * 64 * WSTR;         // [16][66]

    int t = blockIdx.z;
    const float* Wd = (t == 0) ? Wd0 : (t == 1) ? Wd1 : Wd2;
    const float* bd = (t == 0) ? bd0 : (t == 1) ? bd1 : bd2;
    const float* Wc = (t == 0) ? Wc0 : (t == 1) ? Wc1 : Wc2;
    int nlab   = (t == 0) ? 9 : 3;
    int outoff = (t == 0) ? 0 : (t == 1) ? B * 9 : B * 9 + B * 3;

    int r0 = blockIdx.x * 64;
    int b0 = blockIdx.y * 16;

    int tid  = threadIdx.x;
    int wid  = tid >> 5;      // batches 2wid, 2wid+1
    int lane = tid & 31;      // rows lane, lane+32

    const float* P = g_pooled + (size_t)t * B * H;

    // W tile staging map: 1024 float4/tile, 4/thread:
    //   f4id = tid + 256*i -> r = f4id>>4 (0..63), c4 = f4id&15 (0..15)
    int sr  = tid >> 4;
    int sc4 = tid & 15;

    // prologue: issue W tile 0
    {
        const float* src = Wd + (size_t)(r0 + sr) * H + 4 * sc4;
        #pragma unroll
        for (int i = 0; i < 4; i++)
            cp16(&Ws[(sr + 16 * i) * WSTR + 4 * sc4], src + (size_t)(16 * i) * H);
        cp_commit();
    }

    // stage P natural layout (coalesced, conflict-light; overlaps tile-0 cp)
    #pragma unroll
    for (int i = 0; i < 12; i++) {
        int id = tid + 256 * i;       // 0..3071 float4s
        int bb = id / 192;
        int c4 = id - 192 * bb;
        float4 v = *(const float4*)&P[(size_t)(b0 + bb) * H + 4 * c4];
        *(float4*)&Pn[bb * PSTR + 4 * c4] = v;
    }

    float acc00 = 0.f, acc01 = 0.f, acc10 = 0.f, acc11 = 0.f; // [row][batch]
    const int NT = H / KTILE;   // 12 tiles

    for (int it = 0; it < NT; it++) {
        if (it + 1 < NT) {
            int k0n = (it + 1) * KTILE;
            float* dstb = Ws + ((it + 1) & 1) * 64 * WSTR;
            const float* src = Wd + (size_t)(r0 + sr) * H + k0n + 4 * sc4;
            #pragma unroll
            for (int i = 0; i < 4; i++)
                cp16(&dstb[(sr + 16 * i) * WSTR + 4 * sc4], src + (size_t)(16 * i) * H);
            cp_commit();
            cp_wait<1>();
        } else {
            cp_wait<0>();
        }
        __syncthreads();

        const float* Wr0 = Ws + (it & 1) * 64 * WSTR + lane * WSTR;
        const float* Wr1 = Wr0 + 32 * WSTR;
        const float* Pb0 = Pn + (2 * wid) * PSTR + it * KTILE;
        const float* Pb1 = Pb0 + PSTR;

        #pragma unroll
        for (int g = 0; g < KTILE / 4; g++) {
            float4 w0 = *(const float4*)&Wr0[4 * g];
            float4 w1 = *(const float4*)&Wr1[4 * g];
            float4 p0 = *(const float4*)&Pb0[4 * g];
            float4 p1 = *(const float4*)&Pb1[4 * g];
            acc00 += w0.x * p0.x + w0.y * p0.y + w0.z * p0.z + w0.w * p0.w;
            acc01 += w0.x * p1.x + w0.y * p1.y + w0.z * p1.z + w0.w * p1.w;
            acc10 += w1.x * p0.x + w1.y * p0.y + w1.z * p0.z + w1.w * p0.w;
            acc11 += w1.x * p1.x + w1.y * p1.y + w1.z * p1.z + w1.w * p1.w;
        }
        __syncthreads();
    }

    // epilogue: tanh + bias -> Hs  (rows lane, lane+32; batches 2wid, 2wid+1)
    float bd0v = __ldg(&bd[r0 + lane]);
    float bd1v = __ldg(&bd[r0 + lane + 32]);
    Hs[(2 * wid + 0) * 66 + lane]      = tanhf(acc00 + bd0v);
    Hs[(2 * wid + 1) * 66 + lane]      = tanhf(acc01 + bd0v);
    Hs[(2 * wid + 0) * 66 + lane + 32] = tanhf(acc10 + bd1v);
    Hs[(2 * wid + 1) * 66 + lane + 32] = tanhf(acc11 + bd1v);
    __syncthreads();

    // fused classifier: warp wid handles batches 2wid, 2wid+1
    #pragma unroll
    for (int bb = 0; bb < 2; bb++) {
        int bl = 2 * wid + bb;
        float h0v = Hs[bl * 66 + lane];
        float h1v = Hs[bl * 66 + lane + 32];
        for (int l = 0; l < nlab; l++) {
            const float* wr = Wc + (size_t)l * H + r0;
            float s = h0v * __ldg(wr + lane) + h1v * __ldg(wr + lane + 32);
            #pragma unroll
            for (int o = 16; o; o >>= 1) s += __shfl_xor_sync(0xffffffffu, s, o);
            if (lane == 0)
                atomicAdd(&out[outoff + (b0 + bl) * nlab + l], s);
        }
    }
}

// ---------------------------------------------------------------------------
extern "C" void kernel_launch(void* const* d_in, const int* in_sizes, int n_in,
                              void* d_out, int out_size) {
    const float* seq      = (const float*)d_in[0];
    const int*   rel_idx  = (const int*)d_in[1];
    const int*   rel_len  = (const int*)d_in[2];
    const int*   nov_idx  = (const int*)d_in[3];
    const int*   nov_len  = (const int*)d_in[4];
    const int*   dir_idx  = (const int*)d_in[5];
    const int*   dir_len  = (const int*)d_in[6];
    const float* rel_dW   = (const float*)d_in[7];
    const float* rel_db   = (const float*)d_in[8];
    const float* rel_cW   = (const float*)d_in[9];
    const float* rel_cb   = (const float*)d_in[10];
    const float* nov_dW   = (const float*)d_in[11];
    const float* nov_db   = (const float*)d_in[12];
    const float* nov_cW   = (const float*)d_in[13];
    const float* nov_cb   = (const float*)d_in[14];
    const float* dir_dW   = (const float*)d_in[15];
    const float* dir_db   = (const float*)d_in[16];
    const float* dir_cW   = (const float*)d_in[17];
    const float* dir_cb   = (const float*)d_in[18];
    float* out = (float*)d_out;

    static int smem_set = 0;
    if (!smem_set) {
        cudaFuncSetAttribute(dense_kernel,
                             cudaFuncAttributeMaxDynamicSharedMemorySize,
                             DENSE_SMEM);
        smem_set = 1;
    }

    attn_pool_kernel<<<dim3(B, 3, 3), 256>>>(seq, rel_idx, rel_len,
                                             nov_idx, nov_len, dir_idx, dir_len,
                                             rel_cb, nov_cb, dir_cb, out);
    dense_kernel<<<dim3(12, 4, 3), 256, DENSE_SMEM>>>(rel_dW, rel_db, nov_dW, nov_db,
                                                      dir_dW, dir_db,
                                                      rel_cW, nov_cW, dir_cW, out);
}